// round 1
// baseline (speedup 1.0000x reference)
#include <cuda_runtime.h>

// ---------------------------------------------------------------------------
// TabNet DecisionStep, fully fused per 128-row virtual batch (ghost-BN chunk).
// grid = 512 CTAs (one per chunk), 512 threads, ~226KB dynamic smem.
// fp32 FFMA GEMMs (round 1 baseline; tensor cores in a later round).
// ---------------------------------------------------------------------------

#define BTOT   65536
#define DIM    256
#define NCHUNK 512
#define KT     32
#define SMEM_FLOATS 57732
#define SMEM_BYTES  (SMEM_FLOATS * 4)

__device__ float g_loss;

__device__ __forceinline__ float warp_sum(float v) {
#pragma unroll
    for (int o = 16; o; o >>= 1) v += __shfl_xor_sync(0xffffffffu, v, o);
    return v;
}
__device__ __forceinline__ int warp_sum_i(int v) {
#pragma unroll
    for (int o = 16; o; o >>= 1) v += __shfl_xor_sync(0xffffffffu, v, o);
    return v;
}
__device__ __forceinline__ float warp_max(float v) {
#pragma unroll
    for (int o = 16; o; o >>= 1) v = fmaxf(v, __shfl_xor_sync(0xffffffffu, v, o));
    return v;
}

// 128x128 output tile GEMM: out(r,c) = sum_k Zin[r][k] * W[gcol(c)][k]
// gcol(c) = c<64 ? base0+c : base1+(c-64).
// Thread layout: 16 warps = 16 thread-rows (8 rows each), 32 lanes = 32
// thread-cols (4 cols each). A reads are warp-broadcast LDS; W staged in smem
// k-major so B reads are conflict-free LDS.128.
template <int KDIM>
__device__ __forceinline__ void gemm128(const float* __restrict__ Zin, int zstride,
                                        const float* __restrict__ Wg,
                                        int base0, int base1, float* Ws,
                                        float acc[8][4], int tid, int tr, int tc) {
    const int c  = tid >> 2;
    const int gc = (c < 64) ? (base0 + c) : (base1 + c - 64);
    const float* wrow = Wg + (size_t)gc * KDIM + (tid & 3) * 8;
    const int ks = (tid & 3) * 8;

    for (int kb = 0; kb < KDIM; kb += KT) {
        __syncthreads();
        float4 w0 = *(const float4*)(wrow + kb);
        float4 w1 = *(const float4*)(wrow + kb + 4);
        Ws[(ks + 0) * 128 + c] = w0.x;
        Ws[(ks + 1) * 128 + c] = w0.y;
        Ws[(ks + 2) * 128 + c] = w0.z;
        Ws[(ks + 3) * 128 + c] = w0.w;
        Ws[(ks + 4) * 128 + c] = w1.x;
        Ws[(ks + 5) * 128 + c] = w1.y;
        Ws[(ks + 6) * 128 + c] = w1.z;
        Ws[(ks + 7) * 128 + c] = w1.w;
        __syncthreads();
        const float* zrow = Zin + kb;
#pragma unroll 8
        for (int k = 0; k < KT; k++) {
            float4 b4 = *(const float4*)&Ws[k * 128 + tc * 4];
#pragma unroll
            for (int i = 0; i < 8; i++) {
                float av = zrow[(tr * 8 + i) * zstride + k];
                acc[i][0] = fmaf(av, b4.x, acc[i][0]);
                acc[i][1] = fmaf(av, b4.y, acc[i][1]);
                acc[i][2] = fmaf(av, b4.z, acc[i][2]);
                acc[i][3] = fmaf(av, b4.w, acc[i][3]);
            }
        }
    }
}

// Per-column (ghost-BN) stats over the 128 rows of the tile held in acc regs.
// Produces statm[c] (mean), statsc[c] (gamma*rsqrt(var+eps)), statb[c] (beta).
// Linear bias cancels inside BN, so it is never added.
__device__ __forceinline__ void colstats(float acc[8][4], float* red, float* statm,
                                         float* statsc, float* statb,
                                         const float* __restrict__ g,
                                         const float* __restrict__ bt,
                                         int base0, int base1, int tid, int tr, int tc) {
    float ps[4], pq[4];
#pragma unroll
    for (int j = 0; j < 4; j++) {
        float s = 0.f, q = 0.f;
#pragma unroll
        for (int i = 0; i < 8; i++) {
            s += acc[i][j];
            q = fmaf(acc[i][j], acc[i][j], q);
        }
        ps[j] = s;
        pq[j] = q;
    }
    *(float4*)&red[tr * 128 + tc * 4]        = make_float4(ps[0], ps[1], ps[2], ps[3]);
    *(float4*)&red[2048 + tr * 128 + tc * 4] = make_float4(pq[0], pq[1], pq[2], pq[3]);
    __syncthreads();
    if (tid < 128) {
        float s = 0.f, q = 0.f;
#pragma unroll
        for (int t = 0; t < 16; t++) {
            s += red[t * 128 + tid];
            q += red[2048 + t * 128 + tid];
        }
        float m   = s * (1.f / 128.f);
        float var = fmaxf(q * (1.f / 128.f) - m * m, 0.f);
        int gcol  = (tid < 64) ? (base0 + tid) : (base1 + tid - 64);
        statm[tid]  = m;
        statsc[tid] = g[gcol] * rsqrtf(var + 1e-5f);
        statb[tid]  = bt[gcol];
    }
    __syncthreads();
}

// One residual GLU block: Z <- (Z + glu(GBN(Z @ W^T))) * sqrt(0.5)
// Processed in 4 column-pair tiles (cols [ct*64,+64) paired with [256+ct*64,+64)).
// GLU outputs held in registers (ob[64]) until all tiles' GEMMs (which read all
// of Zs) are done, then Z updated in place (or streamed to gmem when FINAL).
template <bool FINAL>
__device__ __forceinline__ void glu_stage(float* Zs, float* ntile, float* Ws, float* red,
                                          float* statm, float* statsc, float* statb,
                                          const float* __restrict__ W,
                                          const float* __restrict__ g,
                                          const float* __restrict__ bt,
                                          float* __restrict__ out, size_t rowbase,
                                          int tid, int tr, int tc) {
    float ob[64];
#pragma unroll
    for (int ct = 0; ct < 4; ct++) {
        float acc[8][4];
#pragma unroll
        for (int i = 0; i < 8; i++) {
            acc[i][0] = acc[i][1] = acc[i][2] = acc[i][3] = 0.f;
        }
        gemm128<256>(Zs, 256, W, ct * 64, 256 + ct * 64, Ws, acc, tid, tr, tc);
        colstats(acc, red, statm, statsc, statb, g, bt, ct * 64, 256 + ct * 64, tid, tr, tc);

        const int c0 = tc * 4;
        float m0 = statm[c0], m1 = statm[c0 + 1], m2 = statm[c0 + 2], m3 = statm[c0 + 3];
        float s0 = statsc[c0], s1 = statsc[c0 + 1], s2 = statsc[c0 + 2], s3 = statsc[c0 + 3];
        float b0 = statb[c0], b1 = statb[c0 + 1], b2 = statb[c0 + 2], b3 = statb[c0 + 3];
#pragma unroll
        for (int i = 0; i < 8; i++) {
            float4 o;
            o.x = (acc[i][0] - m0) * s0 + b0;
            o.y = (acc[i][1] - m1) * s1 + b1;
            o.z = (acc[i][2] - m2) * s2 + b2;
            o.w = (acc[i][3] - m3) * s3 + b3;
            *(float4*)&ntile[(tr * 8 + i) * 128 + c0] = o;
        }
        __syncthreads();
#pragma unroll
        for (int t = 0; t < 16; t++) {
            int e = tid + t * 512;
            int r = e >> 6, cl = e & 63;
            float n1 = ntile[r * 128 + cl];
            float n2 = ntile[r * 128 + 64 + cl];
            ob[ct * 16 + t] = n1 * (1.f / (1.f + __expf(-n2)));
        }
        // next tile's gemm starts with __syncthreads(), guarding ntile reuse
    }
    __syncthreads();
#pragma unroll
    for (int ct = 0; ct < 4; ct++) {
#pragma unroll
        for (int t = 0; t < 16; t++) {
            int e = tid + t * 512;
            int r = e >> 6, cl = e & 63;
            int oc = ct * 64 + cl;
            float z = (Zs[r * 256 + oc] + ob[ct * 16 + t]) * 0.70710678118654752f;
            if (FINAL)
                out[(rowbase + r) * 256 + oc] = z;
            else
                Zs[r * 256 + oc] = z;
        }
    }
    if (!FINAL) __syncthreads();
}

__global__ void __launch_bounds__(512, 1)
tabnet_step(const float* __restrict__ x, const float* __restrict__ a,
            const float* __restrict__ priors,
            const float* __restrict__ Wa, const float* __restrict__ ga,
            const float* __restrict__ bta,
            const float* __restrict__ W0, const float* __restrict__ g0,
            const float* __restrict__ bt0,
            const float* __restrict__ W1, const float* __restrict__ g1,
            const float* __restrict__ bt1, float* __restrict__ out) {
    extern __shared__ float sm[];
    float* Zs     = sm;            // [128][256]  H / mask / Z buffer
    float* As     = sm + 32768;    // [128][128]  a-chunk, later GLU ntile
    float* Ws     = sm + 49152;    // [32][128]   W staging (k-major)
    float* red    = sm + 53248;    // [2][16][128] column partial sums
    float* statm  = sm + 57344;    // [128]
    float* statsc = sm + 57472;    // [128]
    float* statb  = sm + 57600;    // [128]
    float* sloss  = sm + 57728;    // [1]

    const int tid = threadIdx.x;
    const int tr = tid >> 5, tc = tid & 31;
    const size_t rowbase = (size_t)blockIdx.x * 128;

    if (tid == 0) *sloss = 0.f;

    // load a-chunk [128][128] into smem (gemm's leading sync guards it)
    {
        const float4* src = (const float4*)(a + rowbase * 128);
        float4* dst = (float4*)As;
#pragma unroll
        for (int t = 0; t < 8; t++) dst[tid + t * 512] = src[tid + t * 512];
    }

    // ---- Stage A: H = GBN(a @ Wa^T) * priors -> Zs --------------------------
#pragma unroll
    for (int ct = 0; ct < 2; ct++) {
        float acc[8][4];
#pragma unroll
        for (int i = 0; i < 8; i++) {
            acc[i][0] = acc[i][1] = acc[i][2] = acc[i][3] = 0.f;
        }
        gemm128<128>(As, 128, Wa, ct * 128, ct * 128 + 64, Ws, acc, tid, tr, tc);
        colstats(acc, red, statm, statsc, statb, ga, bta, ct * 128, ct * 128 + 64, tid, tr, tc);

        const int c0 = tc * 4;
        float m0 = statm[c0], m1 = statm[c0 + 1], m2 = statm[c0 + 2], m3 = statm[c0 + 3];
        float s0 = statsc[c0], s1 = statsc[c0 + 1], s2 = statsc[c0 + 2], s3 = statsc[c0 + 3];
        float b0 = statb[c0], b1 = statb[c0 + 1], b2 = statb[c0 + 2], b3 = statb[c0 + 3];
#pragma unroll
        for (int i = 0; i < 8; i++) {
            int r = tr * 8 + i;
            float4 pr = *(const float4*)(priors + (rowbase + r) * 256 + ct * 128 + c0);
            float4 o;
            o.x = ((acc[i][0] - m0) * s0 + b0) * pr.x;
            o.y = ((acc[i][1] - m1) * s1 + b1) * pr.y;
            o.z = ((acc[i][2] - m2) * s2 + b2) * pr.z;
            o.w = ((acc[i][3] - m3) * s3 + b3) * pr.w;
            *(float4*)&Zs[r * 256 + ct * 128 + c0] = o;
        }
    }
    __syncthreads();

    // ---- Sparsemax per row (Michelot active-set, exact) + entropy loss -----
    {
        const int lane = tc, w = tr;
        float lacc = 0.f;
        for (int rr = 0; rr < 8; rr++) {
            int r = w * 8 + rr;
            float v[8];
#pragma unroll
            for (int m = 0; m < 8; m++) v[m] = Zs[r * 256 + m * 32 + lane];
            float mx = v[0];
#pragma unroll
            for (int m = 1; m < 8; m++) mx = fmaxf(mx, v[m]);
            mx = warp_max(mx);
#pragma unroll
            for (int m = 0; m < 8; m++) v[m] -= mx;

            unsigned act = 0xffu;
            int cnt = 256;
            float tau = 0.f;
            for (int it = 0; it < 256; it++) {
                float s = 0.f;
#pragma unroll
                for (int m = 0; m < 8; m++)
                    if (act & (1u << m)) s += v[m];
                s = warp_sum(s);
                tau = (s - 1.f) / (float)cnt;
                unsigned na = 0;
                int nc = 0;
#pragma unroll
                for (int m = 0; m < 8; m++)
                    if (v[m] > tau) { na |= (1u << m); nc++; }
                nc = warp_sum_i(nc);
                if (nc == cnt) break;
                act = na;
                cnt = nc;
            }
#pragma unroll
            for (int m = 0; m < 8; m++) {
                float mk = fmaxf(v[m] - tau, 0.f);
                Zs[r * 256 + m * 32 + lane] = mk;
                lacc = fmaf(mk, __logf(mk + 1e-10f), lacc);
            }
        }
        lacc = warp_sum(lacc);
        if (lane == 0) atomicAdd(sloss, lacc);
    }
    __syncthreads();
    if (tid == 0) atomicAdd(&g_loss, *sloss);

    // ---- z0 = x * mask (in place) -------------------------------------------
    {
        const float4* xv = (const float4*)(x + rowbase * 256);
        float4* zz = (float4*)Zs;
#pragma unroll
        for (int t = 0; t < 16; t++) {
            int e = tid + t * 512;
            float4 xx = xv[e];
            float4 zv = zz[e];
            zv.x *= xx.x; zv.y *= xx.y; zv.z *= xx.z; zv.w *= xx.w;
            zz[e] = zv;
        }
    }
    __syncthreads();

    // ---- GLU blocks ----------------------------------------------------------
    glu_stage<false>(Zs, As, Ws, red, statm, statsc, statb, W0, g0, bt0, nullptr,
                     rowbase, tid, tr, tc);
    glu_stage<true>(Zs, As, Ws, red, statm, statsc, statb, W1, g1, bt1, out,
                    rowbase, tid, tr, tc);
}

__global__ void zero_loss_kernel() { g_loss = 0.f; }

__global__ void finalize_kernel(float* out, int out_size) {
    const int zn = BTOT * DIM;
    if (out_size > zn) out[out_size - 1] = -g_loss * (1.f / (float)zn);
}

extern "C" void kernel_launch(void* const* d_in, const int* in_sizes, int n_in,
                              void* d_out, int out_size) {
    const float* x   = (const float*)d_in[0];
    const float* a   = (const float*)d_in[1];
    const float* pr  = (const float*)d_in[2];
    const float* Wa  = (const float*)d_in[3];
    // d_in[4] = b_a : linear bias cancels inside BatchNorm -> unused
    const float* ga  = (const float*)d_in[5];
    const float* bta = (const float*)d_in[6];
    const float* W0  = (const float*)d_in[7];
    // d_in[8] = b0 : cancels
    const float* g0  = (const float*)d_in[9];
    const float* bt0 = (const float*)d_in[10];
    const float* W1  = (const float*)d_in[11];
    // d_in[12] = b1 : cancels
    const float* g1  = (const float*)d_in[13];
    const float* bt1 = (const float*)d_in[14];
    float* out = (float*)d_out;

    cudaFuncSetAttribute(tabnet_step, cudaFuncAttributeMaxDynamicSharedMemorySize,
                         SMEM_BYTES);

    zero_loss_kernel<<<1, 1>>>();
    tabnet_step<<<NCHUNK, 512, SMEM_BYTES>>>(x, a, pr, Wa, ga, bta, W0, g0, bt0,
                                             W1, g1, bt1, out);
    finalize_kernel<<<1, 1>>>(out, out_size);
}

// round 2
// speedup vs baseline: 1.0001x; 1.0001x over previous
#include <cuda_runtime.h>

// ---------------------------------------------------------------------------
// TabNet DecisionStep, fully fused per 128-row virtual batch (ghost-BN chunk).
// grid = 512 CTAs (one per chunk), 512 threads, ~226KB dynamic smem.
// fp32 FFMA GEMMs (round 1 baseline; tensor cores in a later round).
// ---------------------------------------------------------------------------

#define BTOT   65536
#define DIM    256
#define NCHUNK 512
#define KT     32
#define SMEM_FLOATS 57732
#define SMEM_BYTES  (SMEM_FLOATS * 4)

__device__ float g_loss;

__device__ __forceinline__ float warp_sum(float v) {
#pragma unroll
    for (int o = 16; o; o >>= 1) v += __shfl_xor_sync(0xffffffffu, v, o);
    return v;
}
__device__ __forceinline__ int warp_sum_i(int v) {
#pragma unroll
    for (int o = 16; o; o >>= 1) v += __shfl_xor_sync(0xffffffffu, v, o);
    return v;
}
__device__ __forceinline__ float warp_max(float v) {
#pragma unroll
    for (int o = 16; o; o >>= 1) v = fmaxf(v, __shfl_xor_sync(0xffffffffu, v, o));
    return v;
}

// 128x128 output tile GEMM: out(r,c) = sum_k Zin[r][k] * W[gcol(c)][k]
// gcol(c) = c<64 ? base0+c : base1+(c-64).
// Thread layout: 16 warps = 16 thread-rows (8 rows each), 32 lanes = 32
// thread-cols (4 cols each). A reads are warp-broadcast LDS; W staged in smem
// k-major so B reads are conflict-free LDS.128.
template <int KDIM>
__device__ __forceinline__ void gemm128(const float* __restrict__ Zin, int zstride,
                                        const float* __restrict__ Wg,
                                        int base0, int base1, float* Ws,
                                        float acc[8][4], int tid, int tr, int tc) {
    const int c  = tid >> 2;
    const int gc = (c < 64) ? (base0 + c) : (base1 + c - 64);
    const float* wrow = Wg + (size_t)gc * KDIM + (tid & 3) * 8;
    const int ks = (tid & 3) * 8;

    for (int kb = 0; kb < KDIM; kb += KT) {
        __syncthreads();
        float4 w0 = *(const float4*)(wrow + kb);
        float4 w1 = *(const float4*)(wrow + kb + 4);
        Ws[(ks + 0) * 128 + c] = w0.x;
        Ws[(ks + 1) * 128 + c] = w0.y;
        Ws[(ks + 2) * 128 + c] = w0.z;
        Ws[(ks + 3) * 128 + c] = w0.w;
        Ws[(ks + 4) * 128 + c] = w1.x;
        Ws[(ks + 5) * 128 + c] = w1.y;
        Ws[(ks + 6) * 128 + c] = w1.z;
        Ws[(ks + 7) * 128 + c] = w1.w;
        __syncthreads();
        const float* zrow = Zin + kb;
#pragma unroll 8
        for (int k = 0; k < KT; k++) {
            float4 b4 = *(const float4*)&Ws[k * 128 + tc * 4];
#pragma unroll
            for (int i = 0; i < 8; i++) {
                float av = zrow[(tr * 8 + i) * zstride + k];
                acc[i][0] = fmaf(av, b4.x, acc[i][0]);
                acc[i][1] = fmaf(av, b4.y, acc[i][1]);
                acc[i][2] = fmaf(av, b4.z, acc[i][2]);
                acc[i][3] = fmaf(av, b4.w, acc[i][3]);
            }
        }
    }
}

// Per-column (ghost-BN) stats over the 128 rows of the tile held in acc regs.
// Produces statm[c] (mean), statsc[c] (gamma*rsqrt(var+eps)), statb[c] (beta).
// Linear bias cancels inside BN, so it is never added.
__device__ __forceinline__ void colstats(float acc[8][4], float* red, float* statm,
                                         float* statsc, float* statb,
                                         const float* __restrict__ g,
                                         const float* __restrict__ bt,
                                         int base0, int base1, int tid, int tr, int tc) {
    float ps[4], pq[4];
#pragma unroll
    for (int j = 0; j < 4; j++) {
        float s = 0.f, q = 0.f;
#pragma unroll
        for (int i = 0; i < 8; i++) {
            s += acc[i][j];
            q = fmaf(acc[i][j], acc[i][j], q);
        }
        ps[j] = s;
        pq[j] = q;
    }
    *(float4*)&red[tr * 128 + tc * 4]        = make_float4(ps[0], ps[1], ps[2], ps[3]);
    *(float4*)&red[2048 + tr * 128 + tc * 4] = make_float4(pq[0], pq[1], pq[2], pq[3]);
    __syncthreads();
    if (tid < 128) {
        float s = 0.f, q = 0.f;
#pragma unroll
        for (int t = 0; t < 16; t++) {
            s += red[t * 128 + tid];
            q += red[2048 + t * 128 + tid];
        }
        float m   = s * (1.f / 128.f);
        float var = fmaxf(q * (1.f / 128.f) - m * m, 0.f);
        int gcol  = (tid < 64) ? (base0 + tid) : (base1 + tid - 64);
        statm[tid]  = m;
        statsc[tid] = g[gcol] * rsqrtf(var + 1e-5f);
        statb[tid]  = bt[gcol];
    }
    __syncthreads();
}

// One residual GLU block: Z <- (Z + glu(GBN(Z @ W^T))) * sqrt(0.5)
// Processed in 4 column-pair tiles (cols [ct*64,+64) paired with [256+ct*64,+64)).
// GLU outputs held in registers (ob[64]) until all tiles' GEMMs (which read all
// of Zs) are done, then Z updated in place (or streamed to gmem when FINAL).
template <bool FINAL>
__device__ __forceinline__ void glu_stage(float* Zs, float* ntile, float* Ws, float* red,
                                          float* statm, float* statsc, float* statb,
                                          const float* __restrict__ W,
                                          const float* __restrict__ g,
                                          const float* __restrict__ bt,
                                          float* __restrict__ out, size_t rowbase,
                                          int tid, int tr, int tc) {
    float ob[64];
#pragma unroll
    for (int ct = 0; ct < 4; ct++) {
        float acc[8][4];
#pragma unroll
        for (int i = 0; i < 8; i++) {
            acc[i][0] = acc[i][1] = acc[i][2] = acc[i][3] = 0.f;
        }
        gemm128<256>(Zs, 256, W, ct * 64, 256 + ct * 64, Ws, acc, tid, tr, tc);
        colstats(acc, red, statm, statsc, statb, g, bt, ct * 64, 256 + ct * 64, tid, tr, tc);

        const int c0 = tc * 4;
        float m0 = statm[c0], m1 = statm[c0 + 1], m2 = statm[c0 + 2], m3 = statm[c0 + 3];
        float s0 = statsc[c0], s1 = statsc[c0 + 1], s2 = statsc[c0 + 2], s3 = statsc[c0 + 3];
        float b0 = statb[c0], b1 = statb[c0 + 1], b2 = statb[c0 + 2], b3 = statb[c0 + 3];
#pragma unroll
        for (int i = 0; i < 8; i++) {
            float4 o;
            o.x = (acc[i][0] - m0) * s0 + b0;
            o.y = (acc[i][1] - m1) * s1 + b1;
            o.z = (acc[i][2] - m2) * s2 + b2;
            o.w = (acc[i][3] - m3) * s3 + b3;
            *(float4*)&ntile[(tr * 8 + i) * 128 + c0] = o;
        }
        __syncthreads();
#pragma unroll
        for (int t = 0; t < 16; t++) {
            int e = tid + t * 512;
            int r = e >> 6, cl = e & 63;
            float n1 = ntile[r * 128 + cl];
            float n2 = ntile[r * 128 + 64 + cl];
            ob[ct * 16 + t] = n1 * (1.f / (1.f + __expf(-n2)));
        }
        // next tile's gemm starts with __syncthreads(), guarding ntile reuse
    }
    __syncthreads();
#pragma unroll
    for (int ct = 0; ct < 4; ct++) {
#pragma unroll
        for (int t = 0; t < 16; t++) {
            int e = tid + t * 512;
            int r = e >> 6, cl = e & 63;
            int oc = ct * 64 + cl;
            float z = (Zs[r * 256 + oc] + ob[ct * 16 + t]) * 0.70710678118654752f;
            if (FINAL)
                out[(rowbase + r) * 256 + oc] = z;
            else
                Zs[r * 256 + oc] = z;
        }
    }
    if (!FINAL) __syncthreads();
}

__global__ void __launch_bounds__(512, 1)
tabnet_step(const float* __restrict__ x, const float* __restrict__ a,
            const float* __restrict__ priors,
            const float* __restrict__ Wa, const float* __restrict__ ga,
            const float* __restrict__ bta,
            const float* __restrict__ W0, const float* __restrict__ g0,
            const float* __restrict__ bt0,
            const float* __restrict__ W1, const float* __restrict__ g1,
            const float* __restrict__ bt1, float* __restrict__ out) {
    extern __shared__ float sm[];
    float* Zs     = sm;            // [128][256]  H / mask / Z buffer
    float* As     = sm + 32768;    // [128][128]  a-chunk, later GLU ntile
    float* Ws     = sm + 49152;    // [32][128]   W staging (k-major)
    float* red    = sm + 53248;    // [2][16][128] column partial sums
    float* statm  = sm + 57344;    // [128]
    float* statsc = sm + 57472;    // [128]
    float* statb  = sm + 57600;    // [128]
    float* sloss  = sm + 57728;    // [1]

    const int tid = threadIdx.x;
    const int tr = tid >> 5, tc = tid & 31;
    const size_t rowbase = (size_t)blockIdx.x * 128;

    if (tid == 0) *sloss = 0.f;

    // load a-chunk [128][128] into smem (gemm's leading sync guards it)
    {
        const float4* src = (const float4*)(a + rowbase * 128);
        float4* dst = (float4*)As;
#pragma unroll
        for (int t = 0; t < 8; t++) dst[tid + t * 512] = src[tid + t * 512];
    }

    // ---- Stage A: H = GBN(a @ Wa^T) * priors -> Zs --------------------------
#pragma unroll
    for (int ct = 0; ct < 2; ct++) {
        float acc[8][4];
#pragma unroll
        for (int i = 0; i < 8; i++) {
            acc[i][0] = acc[i][1] = acc[i][2] = acc[i][3] = 0.f;
        }
        gemm128<128>(As, 128, Wa, ct * 128, ct * 128 + 64, Ws, acc, tid, tr, tc);
        colstats(acc, red, statm, statsc, statb, ga, bta, ct * 128, ct * 128 + 64, tid, tr, tc);

        const int c0 = tc * 4;
        float m0 = statm[c0], m1 = statm[c0 + 1], m2 = statm[c0 + 2], m3 = statm[c0 + 3];
        float s0 = statsc[c0], s1 = statsc[c0 + 1], s2 = statsc[c0 + 2], s3 = statsc[c0 + 3];
        float b0 = statb[c0], b1 = statb[c0 + 1], b2 = statb[c0 + 2], b3 = statb[c0 + 3];
#pragma unroll
        for (int i = 0; i < 8; i++) {
            int r = tr * 8 + i;
            float4 pr = *(const float4*)(priors + (rowbase + r) * 256 + ct * 128 + c0);
            float4 o;
            o.x = ((acc[i][0] - m0) * s0 + b0) * pr.x;
            o.y = ((acc[i][1] - m1) * s1 + b1) * pr.y;
            o.z = ((acc[i][2] - m2) * s2 + b2) * pr.z;
            o.w = ((acc[i][3] - m3) * s3 + b3) * pr.w;
            *(float4*)&Zs[r * 256 + ct * 128 + c0] = o;
        }
    }
    __syncthreads();

    // ---- Sparsemax per row (Michelot active-set, exact) + entropy loss -----
    {
        const int lane = tc, w = tr;
        float lacc = 0.f;
        for (int rr = 0; rr < 8; rr++) {
            int r = w * 8 + rr;
            float v[8];
#pragma unroll
            for (int m = 0; m < 8; m++) v[m] = Zs[r * 256 + m * 32 + lane];
            float mx = v[0];
#pragma unroll
            for (int m = 1; m < 8; m++) mx = fmaxf(mx, v[m]);
            mx = warp_max(mx);
#pragma unroll
            for (int m = 0; m < 8; m++) v[m] -= mx;

            unsigned act = 0xffu;
            int cnt = 256;
            float tau = 0.f;
            for (int it = 0; it < 256; it++) {
                float s = 0.f;
#pragma unroll
                for (int m = 0; m < 8; m++)
                    if (act & (1u << m)) s += v[m];
                s = warp_sum(s);
                tau = (s - 1.f) / (float)cnt;
                unsigned na = 0;
                int nc = 0;
#pragma unroll
                for (int m = 0; m < 8; m++)
                    if (v[m] > tau) { na |= (1u << m); nc++; }
                nc = warp_sum_i(nc);
                if (nc == cnt) break;
                act = na;
                cnt = nc;
            }
#pragma unroll
            for (int m = 0; m < 8; m++) {
                float mk = fmaxf(v[m] - tau, 0.f);
                Zs[r * 256 + m * 32 + lane] = mk;
                lacc = fmaf(mk, __logf(mk + 1e-10f), lacc);
            }
        }
        lacc = warp_sum(lacc);
        if (lane == 0) atomicAdd(sloss, lacc);
    }
    __syncthreads();
    if (tid == 0) atomicAdd(&g_loss, *sloss);

    // ---- z0 = x * mask (in place) -------------------------------------------
    {
        const float4* xv = (const float4*)(x + rowbase * 256);
        float4* zz = (float4*)Zs;
#pragma unroll
        for (int t = 0; t < 16; t++) {
            int e = tid + t * 512;
            float4 xx = xv[e];
            float4 zv = zz[e];
            zv.x *= xx.x; zv.y *= xx.y; zv.z *= xx.z; zv.w *= xx.w;
            zz[e] = zv;
        }
    }
    __syncthreads();

    // ---- GLU blocks ----------------------------------------------------------
    glu_stage<false>(Zs, As, Ws, red, statm, statsc, statb, W0, g0, bt0, nullptr,
                     rowbase, tid, tr, tc);
    glu_stage<true>(Zs, As, Ws, red, statm, statsc, statb, W1, g1, bt1, out,
                    rowbase, tid, tr, tc);
}

__global__ void zero_loss_kernel() { g_loss = 0.f; }

__global__ void finalize_kernel(float* out, int out_size) {
    const int zn = BTOT * DIM;
    if (out_size > zn) out[out_size - 1] = -g_loss * (1.f / (float)zn);
}

extern "C" void kernel_launch(void* const* d_in, const int* in_sizes, int n_in,
                              void* d_out, int out_size) {
    const float* x   = (const float*)d_in[0];
    const float* a   = (const float*)d_in[1];
    const float* pr  = (const float*)d_in[2];
    const float* Wa  = (const float*)d_in[3];
    // d_in[4] = b_a : linear bias cancels inside BatchNorm -> unused
    const float* ga  = (const float*)d_in[5];
    const float* bta = (const float*)d_in[6];
    const float* W0  = (const float*)d_in[7];
    // d_in[8] = b0 : cancels
    const float* g0  = (const float*)d_in[9];
    const float* bt0 = (const float*)d_in[10];
    const float* W1  = (const float*)d_in[11];
    // d_in[12] = b1 : cancels
    const float* g1  = (const float*)d_in[13];
    const float* bt1 = (const float*)d_in[14];
    float* out = (float*)d_out;

    cudaFuncSetAttribute(tabnet_step, cudaFuncAttributeMaxDynamicSharedMemorySize,
                         SMEM_BYTES);

    zero_loss_kernel<<<1, 1>>>();
    tabnet_step<<<NCHUNK, 512, SMEM_BYTES>>>(x, a, pr, Wa, ga, bta, W0, g0, bt0,
                                             W1, g1, bt1, out);
    finalize_kernel<<<1, 1>>>(out, out_size);
}